// round 13
// baseline (speedup 1.0000x reference)
#include <cuda_runtime.h>
#include <cstdint>
#include <cstddef>

#define N_TOKENS 8192
#define HDIM     1024
#define NHEADS   16
#define SLOTS    16
#define SD       32
#define HD       64
#define FULLMASK 0xffffffffu

typedef unsigned long long u64;

__device__ float4 g_act4[N_TOKENS * NHEADS];
__device__ float  g_WaT[48 * HDIM];                      // WaT[col][k]
__device__ float  g_part[4 * N_TOKENS * 48];             // k-split partials
__device__ float4 g_kv4[(size_t)N_TOKENS * NHEADS * 8];  // kv [tok][head][32]

// ---------------------- helpers ----------------------
__device__ __forceinline__ u64 pack2(float x, float y) {
    u64 r; asm("mov.b64 %0,{%1,%2};" : "=l"(r) : "f"(x), "f"(y)); return r;
}
__device__ __forceinline__ void fma2(u64& d, u64 a, u64 b) {
    asm("fma.rn.f32x2 %0,%1,%2,%0;" : "+l"(d) : "l"(a), "l"(b));
}
__device__ __forceinline__ float2 unpack2(u64 v) {
    float2 r; asm("mov.b64 {%0,%1},%2;" : "=f"(r.x), "=f"(r.y) : "l"(v)); return r;
}
__device__ __forceinline__ float4 f4zero() { return make_float4(0.f, 0.f, 0.f, 0.f); }
__device__ __forceinline__ float4 f4fma(float a, float4 b, float4 c) {
    return make_float4(fmaf(a, b.x, c.x), fmaf(a, b.y, c.y),
                       fmaf(a, b.z, c.z), fmaf(a, b.w, c.w));
}
__device__ __forceinline__ float4 f4add(float4 a, float4 b) {
    return make_float4(a.x + b.x, a.y + b.y, a.z + b.z, a.w + b.w);
}
__device__ __forceinline__ float dot4(float4 a, float4 b) {
    return fmaf(a.x, b.x, fmaf(a.y, b.y, fmaf(a.z, b.z, a.w * b.w)));
}
__device__ __forceinline__ float4 f4shflxor(float4 v, int m) {
    return make_float4(__shfl_xor_sync(FULLMASK, v.x, m),
                       __shfl_xor_sync(FULLMASK, v.y, m),
                       __shfl_xor_sync(FULLMASK, v.z, m),
                       __shfl_xor_sync(FULLMASK, v.w, m));
}

// ---------------------------------------------------------------------------
// Kernel 0: transpose Wa [1024][48] -> g_WaT [48][1024]
// ---------------------------------------------------------------------------
__global__ __launch_bounds__(256) void k_waT(const float* __restrict__ Wa)
{
    const int col = blockIdx.x >> 2;
    const int k   = (blockIdx.x & 3) * 256 + threadIdx.x;
    g_WaT[col * HDIM + k] = Wa[(size_t)k * 48 + col];
}

// ---------------------------------------------------------------------------
// Kernel 1: partial logits GEMM. Block = 128 tok x 48 col x 256-k chunk.
// ---------------------------------------------------------------------------
__global__ __launch_bounds__(256) void k_actions_part(
    const float* __restrict__ hidden)
{
    __shared__ __align__(16) float sA[128][68];
    __shared__ __align__(16) float sWT[48][68];

    const int tid  = threadIdx.x;
    const int ty   = tid >> 3;
    const int tx   = tid & 7;
    const int tile = blockIdx.x >> 2;
    const int kc   = blockIdx.x & 3;
    const int tok0 = tile * 128;
    const float4* hid4 = (const float4*)hidden;
    const float4* waT4 = (const float4*)g_WaT;

    u64 acc[4][6];
#pragma unroll
    for (int t = 0; t < 4; t++)
#pragma unroll
        for (int j = 0; j < 6; j++) acc[t][j] = 0ull;

#pragma unroll
    for (int sub = 0; sub < 4; sub++) {
        const int k4 = kc * 64 + sub * 16;
#pragma unroll
        for (int idx = tid; idx < 2048; idx += 256) {
            int r = idx >> 4, c4 = idx & 15;
            *(float4*)&sA[r][c4 * 4] = hid4[(size_t)(tok0 + r) * 256 + k4 + c4];
        }
#pragma unroll
        for (int idx = tid; idx < 768; idx += 256) {
            int r = idx >> 4, c4 = idx & 15;
            *(float4*)&sWT[r][c4 * 4] = waT4[(size_t)r * 256 + k4 + c4];
        }
        __syncthreads();

#pragma unroll 8
        for (int k2 = 0; k2 < 32; k2++) {
            u64 a[4];
#pragma unroll
            for (int t = 0; t < 4; t++)
                a[t] = *(const u64*)&sA[ty * 4 + t][k2 * 2];
#pragma unroll
            for (int j = 0; j < 6; j++) {
                u64 w = *(const u64*)&sWT[tx * 6 + j][k2 * 2];
                fma2(acc[0][j], a[0], w);
                fma2(acc[1][j], a[1], w);
                fma2(acc[2][j], a[2], w);
                fma2(acc[3][j], a[3], w);
            }
        }
        __syncthreads();
    }

#pragma unroll
    for (int t = 0; t < 4; t++) {
        const size_t base = ((size_t)kc * N_TOKENS + tok0 + ty * 4 + t) * 48 + tx * 6;
#pragma unroll
        for (int j2 = 0; j2 < 3; j2++) {
            float2 pa = unpack2(acc[t][j2 * 2]);
            float2 pb = unpack2(acc[t][j2 * 2 + 1]);
            *(float2*)&g_part[base + j2 * 2] = make_float2(pa.x + pa.y, pb.x + pb.y);
        }
    }
}

// ---------------------------------------------------------------------------
// Kernel 2: kv = hidden-slice @ Wd + bd (block = 128 tok x 1 head, 256 thr),
// PLUS absorbed action reduce+softmax for this block's (tokens, head).
// ---------------------------------------------------------------------------
__global__ __launch_bounds__(256) void k_kv(
    const float* __restrict__ hidden,
    const float* __restrict__ Wd,
    const float* __restrict__ bd,
    const float* __restrict__ ba)
{
    __shared__ __align__(16) float sAT[64 * 128];   // 32 KB
    __shared__ __align__(16) u64   sWd2[64 * 16];   // 8 KB [d][pair]

    const int tid  = threadIdx.x;
    const int head = blockIdx.x & 15;
    const int tok0 = (blockIdx.x >> 4) * 128;
    const int jg   = tid & 7;
    const int tg   = tid >> 3;

    ((float4*)sWd2)[tid]       = ((const float4*)Wd)[tid];
    ((float4*)sWd2)[tid + 256] = ((const float4*)Wd)[tid + 256];

    // absorbed action reduce: thread t < 128 handles token tok0+t, this head
    if (tid < 128) {
        const int token = tok0 + tid;
        float l[3];
#pragma unroll
        for (int j = 0; j < 3; j++) {
            const size_t col = (size_t)token * 48 + head * 3 + j;
            float s = g_part[col]
                    + g_part[(size_t)N_TOKENS * 48 + col]
                    + g_part[(size_t)2 * N_TOKENS * 48 + col]
                    + g_part[(size_t)3 * N_TOKENS * 48 + col];
            l[j] = (s + __ldg(&ba[head * 3 + j])) * 0.125f;
        }
        float mx = fmaxf(l[0], fmaxf(l[1], l[2]));
        float e0 = __expf(l[0] - mx);
        float e1 = __expf(l[1] - mx);
        float e2 = __expf(l[2] - mx);
        float inv = 1.f / (e0 + e1 + e2);
        g_act4[(size_t)token * NHEADS + head] =
            make_float4(e0 * inv, e1 * inv, e2 * inv, 0.f);
    }

    const float4* hid4 = (const float4*)hidden;
#pragma unroll
    for (int k = 0; k < 8; k++) {
        int idx = k * 256 + tid;
        int tok = idx >> 4, c4 = idx & 15;
        float4 v = __ldcs(&hid4[(size_t)(tok0 + tok) * 256 + head * 16 + c4]);
        int d0 = c4 * 4;
        const int tq = tok >> 2, tr = tok & 3;
        sAT[(d0 + 0) * 128 + ((tq ^ ((d0 + 0) & 31)) << 2) + tr] = v.x;
        sAT[(d0 + 1) * 128 + ((tq ^ ((d0 + 1) & 31)) << 2) + tr] = v.y;
        sAT[(d0 + 2) * 128 + ((tq ^ ((d0 + 2) & 31)) << 2) + tr] = v.z;
        sAT[(d0 + 3) * 128 + ((tq ^ ((d0 + 3) & 31)) << 2) + tr] = v.w;
    }
    __syncthreads();

    u64 acc[4][2];
    {
        const u64* bd2 = (const u64*)bd;
        u64 b0 = __ldg(&bd2[jg * 2]);
        u64 b1 = __ldg(&bd2[jg * 2 + 1]);
#pragma unroll
        for (int t = 0; t < 4; t++) { acc[t][0] = b0; acc[t][1] = b1; }
    }

#pragma unroll 16
    for (int d = 0; d < HD; d++) {
        float4 a4 = *(const float4*)&sAT[d * 128 + ((tg ^ (d & 31)) << 2)];
        const u64* wp = &sWd2[d * 16 + jg * 2];
        u64 w0 = wp[0], w1 = wp[1];
        u64 h0 = pack2(a4.x, a4.x), h1 = pack2(a4.y, a4.y);
        u64 h2 = pack2(a4.z, a4.z), h3 = pack2(a4.w, a4.w);
        fma2(acc[0][0], h0, w0); fma2(acc[0][1], h0, w1);
        fma2(acc[1][0], h1, w0); fma2(acc[1][1], h1, w1);
        fma2(acc[2][0], h2, w0); fma2(acc[2][1], h2, w1);
        fma2(acc[3][0], h3, w0); fma2(acc[3][1], h3, w1);
    }

    float4* kvout = g_kv4 + ((size_t)(tok0 + tg * 4) * NHEADS + head) * 8 + jg;
#pragma unroll
    for (int t = 0; t < 4; t++) {
        float2 lo = unpack2(acc[t][0]);
        float2 hi = unpack2(acc[t][1]);
        kvout[t * 128] = make_float4(lo.x, lo.y, hi.x, hi.y);
    }
}

// ---------------------------------------------------------------------------
// Kernel 3 (FUSED): stack update + gate softmax + mem + up-projection + out.
// Block = one token x 4 heads (4 warps, 128 thr). Up-projection repartition:
// thread (wl, lane) -> head = lane&3, d-pair p = wl*8 + (lane>>2), so 4-lane
// groups broadcast-share weight rows (4x LDS dedup). WuT[p][sd] stride 34 u64.
// ---------------------------------------------------------------------------
__global__ __launch_bounds__(128, 7) void k_stack_out(
    const float* __restrict__ hidden,
    const float* __restrict__ stack,
    const float* __restrict__ mask,
    const float* __restrict__ Wg,
    const float* __restrict__ bg,
    const float* __restrict__ Wu,
    const float* __restrict__ bu,
    const float* __restrict__ res_w,
    float* __restrict__ out,
    float* __restrict__ new_stack,
    float* __restrict__ new_mask)
{
    __shared__ __align__(16) u64    sWuT[32 * 34];  // 8.5 KB: WuT[p][sd], pad 2
    __shared__ __align__(16) float4 sMem[4][9];     // padded rows (banks 4*hh)

    const int tid  = threadIdx.x;
    const int wl   = tid >> 5;
    const int lane = tid & 31;
    const int g    = lane >> 3;
    const int c    = lane & 7;

    // WuT fill: f4 i covers u64 j0=2i (sd=i>>4, p0=2*(i&15)) and j0+1.
#pragma unroll
    for (int k = 0; k < 4; k++) {
        int i = k * 128 + tid;
        float4 v = ((const float4*)Wu)[i];
        int sd = i >> 4, p0 = (i & 15) * 2;
        sWuT[p0 * 34 + sd]       = pack2(v.x, v.y);
        sWuT[(p0 + 1) * 34 + sd] = pack2(v.z, v.w);
    }
    __syncthreads();

    const size_t th = (size_t)blockIdx.x * 4 + wl;
    const float4* stk4 = (const float4*)stack + th * 128;

    float4 st[4];
#pragma unroll
    for (int i = 0; i < 4; i++) st[i] = __ldcs(&stk4[i * 32 + lane]);

    const float4 kv4 = __ldg(&g_kv4[th * 8 + c]);
    const float4 act = __ldg(&g_act4[th]);
    const float a_push = act.x, a_pop = act.y, a_noop = act.z;
    const float4 wg4 = __ldg(&((const float4*)Wg)[c]);

    float q[4];
#pragma unroll
    for (int i = 0; i < 4; i++) {
        q[i] = dot4(st[i], wg4);
        q[i] += __shfl_xor_sync(FULLMASK, q[i], 1);
        q[i] += __shfl_xor_sync(FULLMASK, q[i], 2);
        q[i] += __shfl_xor_sync(FULLMASK, q[i], 4);
    }
    float qk = dot4(kv4, wg4);
    qk += __shfl_xor_sync(FULLMASK, qk, 1);
    qk += __shfl_xor_sync(FULLMASK, qk, 2);
    qk += __shfl_xor_sync(FULLMASK, qk, 4);

    // score loop with inline neighbor shuffles (masks stay as L1-hit LDGs)
    const float bgv = __ldg(&bg[0]);
    const float* mk = mask + th * SLOTS;
    float nm[4], e[4];
    float mx = -3.4e38f;
#pragma unroll
    for (int i = 0; i < 4; i++) {
        const int slot = i * 4 + g;
        float sn = (g == 0) ? ((i < 3) ? q[i + 1] : 0.f) : q[i];
        float qn = __shfl_sync(FULLMASK, sn, (lane + 8) & 31);
        float sp = (g == 3) ? ((i > 0) ? q[i - 1] : 0.f) : q[i];
        float qp = __shfl_sync(FULLMASK, sp, (lane + 24) & 31);
        if (g == 0 && i == 0) qp = qk;

        float m  = __ldcs(&mk[slot]);
        float mn = (slot < 15) ? __ldcs(&mk[slot + 1]) : 0.f;
        float mp = (slot > 0)  ? __ldcs(&mk[slot - 1]) : 1.f;
        nm[i] = fmaf(a_push, mp, fmaf(a_pop, mn, a_noop * m));
        float sc = fmaf(a_push, qp, fmaf(a_pop, qn, a_noop * q[i])) + bgv;
        sc += (1.f - nm[i]) * (-1e9f);
        e[i] = sc;
        mx = fmaxf(mx, sc);
    }
    mx = fmaxf(mx, __shfl_xor_sync(FULLMASK, mx, 8));
    mx = fmaxf(mx, __shfl_xor_sync(FULLMASK, mx, 16));
    float ssum = 0.f;
#pragma unroll
    for (int i = 0; i < 4; i++) { e[i] = __expf(e[i] - mx); ssum += e[i]; }
    ssum += __shfl_xor_sync(FULLMASK, ssum, 8);
    ssum += __shfl_xor_sync(FULLMASK, ssum, 16);
    const float ginv = 1.f / ssum;

    if (c == 0) {
#pragma unroll
        for (int i = 0; i < 4; i++)
            __stcs(&new_mask[th * SLOTS + i * 4 + g], nm[i]);
    }

    float4* nst4 = (float4*)new_stack + th * 128;
    float4 acc = f4zero();
#pragma unroll
    for (int i = 0; i < 4; i++) {
        const int slot = i * 4 + g;
        float4 nx = (slot < 15) ? __ldcs(&stk4[i * 32 + lane + 8]) : f4zero();
        float4 pv = (slot > 0)  ? __ldcs(&stk4[i * 32 + lane - 8]) : kv4;
        float4 ns;
        ns.x = fmaf(a_push, pv.x, fmaf(a_pop, nx.x, a_noop * st[i].x));
        ns.y = fmaf(a_push, pv.y, fmaf(a_pop, nx.y, a_noop * st[i].y));
        ns.z = fmaf(a_push, pv.z, fmaf(a_pop, nx.z, a_noop * st[i].z));
        ns.w = fmaf(a_push, pv.w, fmaf(a_pop, nx.w, a_noop * st[i].w));
        __stcs(&nst4[i * 32 + lane], ns);
        acc = f4fma(e[i] * ginv, ns, acc);
    }
    acc = f4add(acc, f4shflxor(acc, 8));
    acc = f4add(acc, f4shflxor(acc, 16));
    if (g == 0) sMem[wl][c] = acc;      // mem[4c..4c+3] of head wl
    __syncthreads();

    // ---- up-projection, block-wide repartition:
    // head hh = lane&3 (sMem row), pair p = wl*8 + (lane>>2).
    const int hh = lane & 3;
    const int p  = wl * 8 + (lane >> 2);
    u64 oacc = __ldg(&((const u64*)bu)[p]);
    const u64* wrow = &sWuT[p * 34];
    const float* memf = (const float*)&sMem[hh][0];
#pragma unroll
    for (int s4 = 0; s4 < 8; s4++) {
        float4 m4 = *(const float4*)&memf[s4 * 4];          // broadcast in group
        ulonglong2 wab = *(const ulonglong2*)&wrow[s4 * 4];     // broadcast
        ulonglong2 wcd = *(const ulonglong2*)&wrow[s4 * 4 + 2]; // broadcast
        fma2(oacc, pack2(m4.x, m4.x), wab.x);
        fma2(oacc, pack2(m4.y, m4.y), wab.y);
        fma2(oacc, pack2(m4.z, m4.z), wcd.x);
        fma2(oacc, pack2(m4.w, m4.w), wcd.y);
    }

    const float rw = __ldg(&res_w[0]);
    const int token = blockIdx.x >> 2;
    const int head  = (blockIdx.x & 3) * 4 + hh;
    const size_t obase = (size_t)token * HDIM + head * HD + 2 * p;
    float2 hv = __ldcs((const float2*)&hidden[obase]);
    float2 ov = unpack2(oacc);
    float2 res;
    res.x = fmaf(ov.x, rw, hv.x);
    res.y = fmaf(ov.y, rw, hv.y);
    __stcs((float2*)&out[obase], res);
}

// ---------------------------------------------------------------------------
extern "C" void kernel_launch(void* const* d_in, const int* in_sizes, int n_in,
                              void* d_out, int out_size)
{
    const float* hidden = (const float*)d_in[0];
    const float* stack  = (const float*)d_in[1];
    const float* mask   = (const float*)d_in[2];
    const float* Wa     = (const float*)d_in[3];
    const float* ba     = (const float*)d_in[4];
    const float* Wd     = (const float*)d_in[5];
    const float* bd     = (const float*)d_in[6];
    const float* Wu     = (const float*)d_in[7];
    const float* bu     = (const float*)d_in[8];
    const float* Wg     = (const float*)d_in[9];
    const float* bg     = (const float*)d_in[10];
    const float* res_w  = (const float*)d_in[11];

    float* out       = (float*)d_out;
    float* new_stack = out + (size_t)N_TOKENS * HDIM;
    float* new_mask  = new_stack + (size_t)N_TOKENS * NHEADS * SLOTS * SD;

    (void)in_sizes; (void)n_in; (void)out_size;

    k_waT<<<192, 256>>>(Wa);
    k_actions_part<<<256, 256>>>(hidden);
    k_kv<<<(N_TOKENS / 128) * NHEADS, 256>>>(hidden, Wd, bd, ba);
    k_stack_out<<<N_TOKENS * NHEADS / 4, 128>>>(hidden, stack, mask, Wg, bg,
                                                Wu, bu, res_w,
                                                out, new_stack, new_mask);
}

// round 14
// speedup vs baseline: 1.0598x; 1.0598x over previous
#include <cuda_runtime.h>
#include <cstdint>
#include <cstddef>

#define N_TOKENS 8192
#define HDIM     1024
#define NHEADS   16
#define SLOTS    16
#define SD       32
#define HD       64
#define FULLMASK 0xffffffffu

typedef unsigned long long u64;

__device__ float4 g_act4[N_TOKENS * NHEADS];
__device__ float  g_WaT[48 * HDIM];                      // WaT[col][k]
__device__ float  g_part[4 * N_TOKENS * 48];             // k-split partials
__device__ float4 g_kv4[(size_t)N_TOKENS * NHEADS * 8];  // kv [tok][head][32]

// ---------------------- helpers ----------------------
__device__ __forceinline__ u64 pack2(float x, float y) {
    u64 r; asm("mov.b64 %0,{%1,%2};" : "=l"(r) : "f"(x), "f"(y)); return r;
}
__device__ __forceinline__ void fma2(u64& d, u64 a, u64 b) {
    asm("fma.rn.f32x2 %0,%1,%2,%0;" : "+l"(d) : "l"(a), "l"(b));
}
__device__ __forceinline__ float2 unpack2(u64 v) {
    float2 r; asm("mov.b64 {%0,%1},%2;" : "=f"(r.x), "=f"(r.y) : "l"(v)); return r;
}
__device__ __forceinline__ float4 f4zero() { return make_float4(0.f, 0.f, 0.f, 0.f); }
__device__ __forceinline__ float4 f4fma(float a, float4 b, float4 c) {
    return make_float4(fmaf(a, b.x, c.x), fmaf(a, b.y, c.y),
                       fmaf(a, b.z, c.z), fmaf(a, b.w, c.w));
}
__device__ __forceinline__ float4 f4add(float4 a, float4 b) {
    return make_float4(a.x + b.x, a.y + b.y, a.z + b.z, a.w + b.w);
}
__device__ __forceinline__ float dot4(float4 a, float4 b) {
    return fmaf(a.x, b.x, fmaf(a.y, b.y, fmaf(a.z, b.z, a.w * b.w)));
}
__device__ __forceinline__ float4 f4shflxor(float4 v, int m) {
    return make_float4(__shfl_xor_sync(FULLMASK, v.x, m),
                       __shfl_xor_sync(FULLMASK, v.y, m),
                       __shfl_xor_sync(FULLMASK, v.z, m),
                       __shfl_xor_sync(FULLMASK, v.w, m));
}

// ---------------------------------------------------------------------------
// Kernel 0: transpose Wa [1024][48] -> g_WaT [48][1024]
// ---------------------------------------------------------------------------
__global__ __launch_bounds__(256) void k_waT(const float* __restrict__ Wa)
{
    const int col = blockIdx.x >> 2;
    const int k   = (blockIdx.x & 3) * 256 + threadIdx.x;
    g_WaT[col * HDIM + k] = Wa[(size_t)k * 48 + col];
}

// ---------------------------------------------------------------------------
// Kernel 1: partial logits GEMM. Block = 128 tok x 48 col x 256-k chunk.
// ---------------------------------------------------------------------------
__global__ __launch_bounds__(256) void k_actions_part(
    const float* __restrict__ hidden)
{
    __shared__ __align__(16) float sA[128][68];
    __shared__ __align__(16) float sWT[48][68];

    const int tid  = threadIdx.x;
    const int ty   = tid >> 3;
    const int tx   = tid & 7;
    const int tile = blockIdx.x >> 2;
    const int kc   = blockIdx.x & 3;
    const int tok0 = tile * 128;
    const float4* hid4 = (const float4*)hidden;
    const float4* waT4 = (const float4*)g_WaT;

    u64 acc[4][6];
#pragma unroll
    for (int t = 0; t < 4; t++)
#pragma unroll
        for (int j = 0; j < 6; j++) acc[t][j] = 0ull;

#pragma unroll
    for (int sub = 0; sub < 4; sub++) {
        const int k4 = kc * 64 + sub * 16;
#pragma unroll
        for (int idx = tid; idx < 2048; idx += 256) {
            int r = idx >> 4, c4 = idx & 15;
            *(float4*)&sA[r][c4 * 4] = hid4[(size_t)(tok0 + r) * 256 + k4 + c4];
        }
#pragma unroll
        for (int idx = tid; idx < 768; idx += 256) {
            int r = idx >> 4, c4 = idx & 15;
            *(float4*)&sWT[r][c4 * 4] = waT4[(size_t)r * 256 + k4 + c4];
        }
        __syncthreads();

#pragma unroll 8
        for (int k2 = 0; k2 < 32; k2++) {
            u64 a[4];
#pragma unroll
            for (int t = 0; t < 4; t++)
                a[t] = *(const u64*)&sA[ty * 4 + t][k2 * 2];
#pragma unroll
            for (int j = 0; j < 6; j++) {
                u64 w = *(const u64*)&sWT[tx * 6 + j][k2 * 2];
                fma2(acc[0][j], a[0], w);
                fma2(acc[1][j], a[1], w);
                fma2(acc[2][j], a[2], w);
                fma2(acc[3][j], a[3], w);
            }
        }
        __syncthreads();
    }

#pragma unroll
    for (int t = 0; t < 4; t++) {
        const size_t base = ((size_t)kc * N_TOKENS + tok0 + ty * 4 + t) * 48 + tx * 6;
#pragma unroll
        for (int j2 = 0; j2 < 3; j2++) {
            float2 pa = unpack2(acc[t][j2 * 2]);
            float2 pb = unpack2(acc[t][j2 * 2 + 1]);
            *(float2*)&g_part[base + j2 * 2] = make_float2(pa.x + pa.y, pb.x + pb.y);
        }
    }
}

// ---------------------------------------------------------------------------
// Kernel 2: kv = hidden-slice @ Wd + bd (block = 128 tok x 1 head, 256 thr),
// PLUS absorbed action reduce+softmax for this block's (tokens, head).
// ---------------------------------------------------------------------------
__global__ __launch_bounds__(256) void k_kv(
    const float* __restrict__ hidden,
    const float* __restrict__ Wd,
    const float* __restrict__ bd,
    const float* __restrict__ ba)
{
    __shared__ __align__(16) float sAT[64 * 128];   // 32 KB
    __shared__ __align__(16) u64   sWd2[64 * 16];   // 8 KB [d][pair]

    const int tid  = threadIdx.x;
    const int head = blockIdx.x & 15;
    const int tok0 = (blockIdx.x >> 4) * 128;
    const int jg   = tid & 7;
    const int tg   = tid >> 3;

    ((float4*)sWd2)[tid]       = ((const float4*)Wd)[tid];
    ((float4*)sWd2)[tid + 256] = ((const float4*)Wd)[tid + 256];

    // absorbed action reduce: thread t < 128 handles token tok0+t, this head
    if (tid < 128) {
        const int token = tok0 + tid;
        float l[3];
#pragma unroll
        for (int j = 0; j < 3; j++) {
            const size_t col = (size_t)token * 48 + head * 3 + j;
            float s = g_part[col]
                    + g_part[(size_t)N_TOKENS * 48 + col]
                    + g_part[(size_t)2 * N_TOKENS * 48 + col]
                    + g_part[(size_t)3 * N_TOKENS * 48 + col];
            l[j] = (s + __ldg(&ba[head * 3 + j])) * 0.125f;
        }
        float mx = fmaxf(l[0], fmaxf(l[1], l[2]));
        float e0 = __expf(l[0] - mx);
        float e1 = __expf(l[1] - mx);
        float e2 = __expf(l[2] - mx);
        float inv = 1.f / (e0 + e1 + e2);
        g_act4[(size_t)token * NHEADS + head] =
            make_float4(e0 * inv, e1 * inv, e2 * inv, 0.f);
    }

    const float4* hid4 = (const float4*)hidden;
#pragma unroll
    for (int k = 0; k < 8; k++) {
        int idx = k * 256 + tid;
        int tok = idx >> 4, c4 = idx & 15;
        float4 v = __ldcs(&hid4[(size_t)(tok0 + tok) * 256 + head * 16 + c4]);
        int d0 = c4 * 4;
        const int tq = tok >> 2, tr = tok & 3;
        sAT[(d0 + 0) * 128 + ((tq ^ ((d0 + 0) & 31)) << 2) + tr] = v.x;
        sAT[(d0 + 1) * 128 + ((tq ^ ((d0 + 1) & 31)) << 2) + tr] = v.y;
        sAT[(d0 + 2) * 128 + ((tq ^ ((d0 + 2) & 31)) << 2) + tr] = v.z;
        sAT[(d0 + 3) * 128 + ((tq ^ ((d0 + 3) & 31)) << 2) + tr] = v.w;
    }
    __syncthreads();

    u64 acc[4][2];
    {
        const u64* bd2 = (const u64*)bd;
        u64 b0 = __ldg(&bd2[jg * 2]);
        u64 b1 = __ldg(&bd2[jg * 2 + 1]);
#pragma unroll
        for (int t = 0; t < 4; t++) { acc[t][0] = b0; acc[t][1] = b1; }
    }

#pragma unroll 16
    for (int d = 0; d < HD; d++) {
        float4 a4 = *(const float4*)&sAT[d * 128 + ((tg ^ (d & 31)) << 2)];
        const u64* wp = &sWd2[d * 16 + jg * 2];
        u64 w0 = wp[0], w1 = wp[1];
        u64 h0 = pack2(a4.x, a4.x), h1 = pack2(a4.y, a4.y);
        u64 h2 = pack2(a4.z, a4.z), h3 = pack2(a4.w, a4.w);
        fma2(acc[0][0], h0, w0); fma2(acc[0][1], h0, w1);
        fma2(acc[1][0], h1, w0); fma2(acc[1][1], h1, w1);
        fma2(acc[2][0], h2, w0); fma2(acc[2][1], h2, w1);
        fma2(acc[3][0], h3, w0); fma2(acc[3][1], h3, w1);
    }

    float4* kvout = g_kv4 + ((size_t)(tok0 + tg * 4) * NHEADS + head) * 8 + jg;
#pragma unroll
    for (int t = 0; t < 4; t++) {
        float2 lo = unpack2(acc[t][0]);
        float2 hi = unpack2(acc[t][1]);
        kvout[t * 128] = make_float4(lo.x, lo.y, hi.x, hi.y);
    }
}

// ---------------------------------------------------------------------------
// Kernel 3 (FUSED): stack update + gate softmax + mem + up-projection + out.
// Block = one token x 4 heads (4 warps). R12 body; up-projection repartition
// with CONFLICT-FREE transposed fill:
//   fill: thread (wl,lane) owns WuT column p=lane, sd in [wl*8, wl*8+8)
//         via coalesced LDG.64 rows + STS.128 (banks 4*lane%32 distinct/phase)
//   read: head hh = lane&3, pair p = wl*8+(lane>>2) -> 4-lane broadcast groups
// ---------------------------------------------------------------------------
__global__ __launch_bounds__(128, 7) void k_stack_out(
    const float* __restrict__ hidden,
    const float* __restrict__ stack,
    const float* __restrict__ mask,
    const float* __restrict__ Wg,
    const float* __restrict__ bg,
    const float* __restrict__ Wu,
    const float* __restrict__ bu,
    const float* __restrict__ res_w,
    float* __restrict__ out,
    float* __restrict__ new_stack,
    float* __restrict__ new_mask)
{
    __shared__ __align__(16) u64    sWuT[32 * 34];  // 8.5 KB: WuT[p][sd], pad 2
    __shared__ __align__(16) float4 sMem[4][9];     // padded rows

    const int tid  = threadIdx.x;
    const int wl   = tid >> 5;
    const int lane = tid & 31;
    const int g    = lane >> 3;
    const int c    = lane & 7;

    // ---- conflict-free WuT fill ----
    {
        const u64* Wu2 = (const u64*)Wu;
#pragma unroll
        for (int k = 0; k < 2; k++) {
            const int sd0 = wl * 8 + k * 4;
            u64 w0 = __ldg(&Wu2[(size_t)(sd0 + 0) * 32 + lane]);  // coalesced 256B
            u64 w1 = __ldg(&Wu2[(size_t)(sd0 + 1) * 32 + lane]);
            u64 w2 = __ldg(&Wu2[(size_t)(sd0 + 2) * 32 + lane]);
            u64 w3 = __ldg(&Wu2[(size_t)(sd0 + 3) * 32 + lane]);
            ulonglong2 a; a.x = w0; a.y = w1;
            ulonglong2 b; b.x = w2; b.y = w3;
            *(ulonglong2*)&sWuT[lane * 34 + sd0]     = a;   // STS.128, CF
            *(ulonglong2*)&sWuT[lane * 34 + sd0 + 2] = b;
        }
    }
    __syncthreads();

    const size_t th = (size_t)blockIdx.x * 4 + wl;
    const float4* stk4 = (const float4*)stack + th * 128;

    float4 st[4];
#pragma unroll
    for (int i = 0; i < 4; i++) st[i] = __ldcs(&stk4[i * 32 + lane]);

    const float4 kv4 = __ldg(&g_kv4[th * 8 + c]);
    const float4 act = __ldg(&g_act4[th]);
    const float a_push = act.x, a_pop = act.y, a_noop = act.z;
    const float4 wg4 = __ldg(&((const float4*)Wg)[c]);

    float q[4];
#pragma unroll
    for (int i = 0; i < 4; i++) {
        q[i] = dot4(st[i], wg4);
        q[i] += __shfl_xor_sync(FULLMASK, q[i], 1);
        q[i] += __shfl_xor_sync(FULLMASK, q[i], 2);
        q[i] += __shfl_xor_sync(FULLMASK, q[i], 4);
    }
    float qk = dot4(kv4, wg4);
    qk += __shfl_xor_sync(FULLMASK, qk, 1);
    qk += __shfl_xor_sync(FULLMASK, qk, 2);
    qk += __shfl_xor_sync(FULLMASK, qk, 4);

    float qn[4], qp[4];
#pragma unroll
    for (int i = 0; i < 4; i++) {
        float sn = (g == 0) ? ((i < 3) ? q[i + 1] : 0.f) : q[i];
        qn[i] = __shfl_sync(FULLMASK, sn, (lane + 8) & 31);
        float sp = (g == 3) ? ((i > 0) ? q[i - 1] : 0.f) : q[i];
        qp[i] = __shfl_sync(FULLMASK, sp, (lane + 24) & 31);
    }
    if (g == 0) qp[0] = qk;

    const float bgv = __ldg(&bg[0]);
    const float* mk = mask + th * SLOTS;
    float nm[4], e[4];
    float mx = -3.4e38f;
#pragma unroll
    for (int i = 0; i < 4; i++) {
        const int slot = i * 4 + g;
        float m  = __ldcs(&mk[slot]);
        float mn = (slot < 15) ? __ldcs(&mk[slot + 1]) : 0.f;
        float mp = (slot > 0)  ? __ldcs(&mk[slot - 1]) : 1.f;
        nm[i] = fmaf(a_push, mp, fmaf(a_pop, mn, a_noop * m));
        float sc = fmaf(a_push, qp[i], fmaf(a_pop, qn[i], a_noop * q[i])) + bgv;
        sc += (1.f - nm[i]) * (-1e9f);
        e[i] = sc;
        mx = fmaxf(mx, sc);
    }
    mx = fmaxf(mx, __shfl_xor_sync(FULLMASK, mx, 8));
    mx = fmaxf(mx, __shfl_xor_sync(FULLMASK, mx, 16));
    float ssum = 0.f;
#pragma unroll
    for (int i = 0; i < 4; i++) { e[i] = __expf(e[i] - mx); ssum += e[i]; }
    ssum += __shfl_xor_sync(FULLMASK, ssum, 8);
    ssum += __shfl_xor_sync(FULLMASK, ssum, 16);
    const float ginv = 1.f / ssum;

    if (c == 0) {
#pragma unroll
        for (int i = 0; i < 4; i++)
            __stcs(&new_mask[th * SLOTS + i * 4 + g], nm[i]);
    }

    float4* nst4 = (float4*)new_stack + th * 128;
    float4 acc = f4zero();
#pragma unroll
    for (int i = 0; i < 4; i++) {
        const int slot = i * 4 + g;
        float4 nx = (slot < 15) ? __ldcs(&stk4[i * 32 + lane + 8]) : f4zero();
        float4 pv = (slot > 0)  ? __ldcs(&stk4[i * 32 + lane - 8]) : kv4;
        float4 ns;
        ns.x = fmaf(a_push, pv.x, fmaf(a_pop, nx.x, a_noop * st[i].x));
        ns.y = fmaf(a_push, pv.y, fmaf(a_pop, nx.y, a_noop * st[i].y));
        ns.z = fmaf(a_push, pv.z, fmaf(a_pop, nx.z, a_noop * st[i].z));
        ns.w = fmaf(a_push, pv.w, fmaf(a_pop, nx.w, a_noop * st[i].w));
        __stcs(&nst4[i * 32 + lane], ns);
        acc = f4fma(e[i] * ginv, ns, acc);
    }
    acc = f4add(acc, f4shflxor(acc, 8));
    acc = f4add(acc, f4shflxor(acc, 16));
    if (g == 0) sMem[wl][c] = acc;      // mem[4c..4c+3] of head wl
    __syncthreads();

    // ---- up-projection, block-wide repartition (broadcast-shared weights)
    const int hh = lane & 3;
    const int p  = wl * 8 + (lane >> 2);
    u64 oacc = __ldg(&((const u64*)bu)[p]);
    const u64* wrow = &sWuT[p * 34];
    const float* memf = (const float*)&sMem[hh][0];
#pragma unroll
    for (int s4 = 0; s4 < 8; s4++) {
        float4 m4 = *(const float4*)&memf[s4 * 4];              // bcast LDS.128
        ulonglong2 wab = *(const ulonglong2*)&wrow[s4 * 4];     // bcast LDS.128
        ulonglong2 wcd = *(const ulonglong2*)&wrow[s4 * 4 + 2];
        fma2(oacc, pack2(m4.x, m4.x), wab.x);
        fma2(oacc, pack2(m4.y, m4.y), wab.y);
        fma2(oacc, pack2(m4.z, m4.z), wcd.x);
        fma2(oacc, pack2(m4.w, m4.w), wcd.y);
    }

    const float rw = __ldg(&res_w[0]);
    const int token = blockIdx.x >> 2;
    const int head  = (blockIdx.x & 3) * 4 + hh;
    const size_t obase = (size_t)token * HDIM + head * HD + 2 * p;
    float2 hv = __ldcs((const float2*)&hidden[obase]);
    float2 ov = unpack2(oacc);
    float2 res;
    res.x = fmaf(ov.x, rw, hv.x);
    res.y = fmaf(ov.y, rw, hv.y);
    __stcs((float2*)&out[obase], res);
}

// ---------------------------------------------------------------------------
extern "C" void kernel_launch(void* const* d_in, const int* in_sizes, int n_in,
                              void* d_out, int out_size)
{
    const float* hidden = (const float*)d_in[0];
    const float* stack  = (const float*)d_in[1];
    const float* mask   = (const float*)d_in[2];
    const float* Wa     = (const float*)d_in[3];
    const float* ba     = (const float*)d_in[4];
    const float* Wd     = (const float*)d_in[5];
    const float* bd     = (const float*)d_in[6];
    const float* Wu     = (const float*)d_in[7];
    const float* bu     = (const float*)d_in[8];
    const float* Wg     = (const float*)d_in[9];
    const float* bg     = (const float*)d_in[10];
    const float* res_w  = (const float*)d_in[11];

    float* out       = (float*)d_out;
    float* new_stack = out + (size_t)N_TOKENS * HDIM;
    float* new_mask  = new_stack + (size_t)N_TOKENS * NHEADS * SLOTS * SD;

    (void)in_sizes; (void)n_in; (void)out_size;

    k_waT<<<192, 256>>>(Wa);
    k_actions_part<<<256, 256>>>(hidden);
    k_kv<<<(N_TOKENS / 128) * NHEADS, 256>>>(hidden, Wd, bd, ba);
    k_stack_out<<<N_TOKENS * NHEADS / 4, 128>>>(hidden, stack, mask, Wg, bg,
                                                Wu, bu, res_w,
                                                out, new_stack, new_mask);
}

// round 15
// speedup vs baseline: 1.0967x; 1.0348x over previous
#include <cuda_runtime.h>
#include <cstdint>
#include <cstddef>

#define N_TOKENS 8192
#define HDIM     1024
#define NHEADS   16
#define SLOTS    16
#define SD       32
#define HD       64
#define FULLMASK 0xffffffffu

typedef unsigned long long u64;

__device__ float4 g_act4[N_TOKENS * NHEADS];
__device__ float  g_WaT[48 * HDIM];                      // WaT[col][k]
__device__ float  g_part[4 * N_TOKENS * 48];             // k-split partials
__device__ float4 g_kv4[(size_t)N_TOKENS * NHEADS * 8];  // kv [tok][head][32]

// ---------------------- helpers ----------------------
__device__ __forceinline__ u64 pack2(float x, float y) {
    u64 r; asm("mov.b64 %0,{%1,%2};" : "=l"(r) : "f"(x), "f"(y)); return r;
}
__device__ __forceinline__ void fma2(u64& d, u64 a, u64 b) {
    asm("fma.rn.f32x2 %0,%1,%2,%0;" : "+l"(d) : "l"(a), "l"(b));
}
__device__ __forceinline__ float2 unpack2(u64 v) {
    float2 r; asm("mov.b64 {%0,%1},%2;" : "=f"(r.x), "=f"(r.y) : "l"(v)); return r;
}
__device__ __forceinline__ float4 f4zero() { return make_float4(0.f, 0.f, 0.f, 0.f); }
__device__ __forceinline__ float4 f4fma(float a, float4 b, float4 c) {
    return make_float4(fmaf(a, b.x, c.x), fmaf(a, b.y, c.y),
                       fmaf(a, b.z, c.z), fmaf(a, b.w, c.w));
}
__device__ __forceinline__ float4 f4add(float4 a, float4 b) {
    return make_float4(a.x + b.x, a.y + b.y, a.z + b.z, a.w + b.w);
}
__device__ __forceinline__ float dot4(float4 a, float4 b) {
    return fmaf(a.x, b.x, fmaf(a.y, b.y, fmaf(a.z, b.z, a.w * b.w)));
}
__device__ __forceinline__ float4 f4shflxor(float4 v, int m) {
    return make_float4(__shfl_xor_sync(FULLMASK, v.x, m),
                       __shfl_xor_sync(FULLMASK, v.y, m),
                       __shfl_xor_sync(FULLMASK, v.z, m),
                       __shfl_xor_sync(FULLMASK, v.w, m));
}
__device__ __forceinline__ float4 f4shfl(float4 v, int src) {
    return make_float4(__shfl_sync(FULLMASK, v.x, src),
                       __shfl_sync(FULLMASK, v.y, src),
                       __shfl_sync(FULLMASK, v.z, src),
                       __shfl_sync(FULLMASK, v.w, src));
}

// ---------------------------------------------------------------------------
// Kernel 0: transpose Wa [1024][48] -> g_WaT [48][1024]
// ---------------------------------------------------------------------------
__global__ __launch_bounds__(256) void k_waT(const float* __restrict__ Wa)
{
    const int col = blockIdx.x >> 2;
    const int k   = (blockIdx.x & 3) * 256 + threadIdx.x;
    g_WaT[col * HDIM + k] = Wa[(size_t)k * 48 + col];
}

// ---------------------------------------------------------------------------
// Kernel 1: partial logits GEMM. Block = 128 tok x 48 col x 256-k chunk.
// ---------------------------------------------------------------------------
__global__ __launch_bounds__(256) void k_actions_part(
    const float* __restrict__ hidden)
{
    __shared__ __align__(16) float sA[128][68];
    __shared__ __align__(16) float sWT[48][68];

    const int tid  = threadIdx.x;
    const int ty   = tid >> 3;
    const int tx   = tid & 7;
    const int tile = blockIdx.x >> 2;
    const int kc   = blockIdx.x & 3;
    const int tok0 = tile * 128;
    const float4* hid4 = (const float4*)hidden;
    const float4* waT4 = (const float4*)g_WaT;

    u64 acc[4][6];
#pragma unroll
    for (int t = 0; t < 4; t++)
#pragma unroll
        for (int j = 0; j < 6; j++) acc[t][j] = 0ull;

#pragma unroll
    for (int sub = 0; sub < 4; sub++) {
        const int k4 = kc * 64 + sub * 16;
#pragma unroll
        for (int idx = tid; idx < 2048; idx += 256) {
            int r = idx >> 4, c4 = idx & 15;
            *(float4*)&sA[r][c4 * 4] = hid4[(size_t)(tok0 + r) * 256 + k4 + c4];
        }
#pragma unroll
        for (int idx = tid; idx < 768; idx += 256) {
            int r = idx >> 4, c4 = idx & 15;
            *(float4*)&sWT[r][c4 * 4] = waT4[(size_t)r * 256 + k4 + c4];
        }
        __syncthreads();

#pragma unroll 8
        for (int k2 = 0; k2 < 32; k2++) {
            u64 a[4];
#pragma unroll
            for (int t = 0; t < 4; t++)
                a[t] = *(const u64*)&sA[ty * 4 + t][k2 * 2];
#pragma unroll
            for (int j = 0; j < 6; j++) {
                u64 w = *(const u64*)&sWT[tx * 6 + j][k2 * 2];
                fma2(acc[0][j], a[0], w);
                fma2(acc[1][j], a[1], w);
                fma2(acc[2][j], a[2], w);
                fma2(acc[3][j], a[3], w);
            }
        }
        __syncthreads();
    }

#pragma unroll
    for (int t = 0; t < 4; t++) {
        const size_t base = ((size_t)kc * N_TOKENS + tok0 + ty * 4 + t) * 48 + tx * 6;
#pragma unroll
        for (int j2 = 0; j2 < 3; j2++) {
            float2 pa = unpack2(acc[t][j2 * 2]);
            float2 pb = unpack2(acc[t][j2 * 2 + 1]);
            *(float2*)&g_part[base + j2 * 2] = make_float2(pa.x + pa.y, pb.x + pb.y);
        }
    }
}

// ---------------------------------------------------------------------------
// Kernel 2: kv = hidden-slice @ Wd + bd (block = 128 tok x 1 head, 256 thr),
// PLUS absorbed action reduce+softmax for this block's (tokens, head).
// ---------------------------------------------------------------------------
__global__ __launch_bounds__(256) void k_kv(
    const float* __restrict__ hidden,
    const float* __restrict__ Wd,
    const float* __restrict__ bd,
    const float* __restrict__ ba)
{
    __shared__ __align__(16) float sAT[64 * 128];   // 32 KB
    __shared__ __align__(16) u64   sWd2[64 * 16];   // 8 KB [d][pair]

    const int tid  = threadIdx.x;
    const int head = blockIdx.x & 15;
    const int tok0 = (blockIdx.x >> 4) * 128;
    const int jg   = tid & 7;
    const int tg   = tid >> 3;

    ((float4*)sWd2)[tid]       = ((const float4*)Wd)[tid];
    ((float4*)sWd2)[tid + 256] = ((const float4*)Wd)[tid + 256];

    // absorbed action reduce: thread t < 128 handles token tok0+t, this head
    if (tid < 128) {
        const int token = tok0 + tid;
        float l[3];
#pragma unroll
        for (int j = 0; j < 3; j++) {
            const size_t col = (size_t)token * 48 + head * 3 + j;
            float s = g_part[col]
                    + g_part[(size_t)N_TOKENS * 48 + col]
                    + g_part[(size_t)2 * N_TOKENS * 48 + col]
                    + g_part[(size_t)3 * N_TOKENS * 48 + col];
            l[j] = (s + __ldg(&ba[head * 3 + j])) * 0.125f;
        }
        float mx = fmaxf(l[0], fmaxf(l[1], l[2]));
        float e0 = __expf(l[0] - mx);
        float e1 = __expf(l[1] - mx);
        float e2 = __expf(l[2] - mx);
        float inv = 1.f / (e0 + e1 + e2);
        g_act4[(size_t)token * NHEADS + head] =
            make_float4(e0 * inv, e1 * inv, e2 * inv, 0.f);
    }

    const float4* hid4 = (const float4*)hidden;
#pragma unroll
    for (int k = 0; k < 8; k++) {
        int idx = k * 256 + tid;
        int tok = idx >> 4, c4 = idx & 15;
        float4 v = __ldcs(&hid4[(size_t)(tok0 + tok) * 256 + head * 16 + c4]);
        int d0 = c4 * 4;
        const int tq = tok >> 2, tr = tok & 3;
        sAT[(d0 + 0) * 128 + ((tq ^ ((d0 + 0) & 31)) << 2) + tr] = v.x;
        sAT[(d0 + 1) * 128 + ((tq ^ ((d0 + 1) & 31)) << 2) + tr] = v.y;
        sAT[(d0 + 2) * 128 + ((tq ^ ((d0 + 2) & 31)) << 2) + tr] = v.z;
        sAT[(d0 + 3) * 128 + ((tq ^ ((d0 + 3) & 31)) << 2) + tr] = v.w;
    }
    __syncthreads();

    u64 acc[4][2];
    {
        const u64* bd2 = (const u64*)bd;
        u64 b0 = __ldg(&bd2[jg * 2]);
        u64 b1 = __ldg(&bd2[jg * 2 + 1]);
#pragma unroll
        for (int t = 0; t < 4; t++) { acc[t][0] = b0; acc[t][1] = b1; }
    }

#pragma unroll 16
    for (int d = 0; d < HD; d++) {
        float4 a4 = *(const float4*)&sAT[d * 128 + ((tg ^ (d & 31)) << 2)];
        const u64* wp = &sWd2[d * 16 + jg * 2];
        u64 w0 = wp[0], w1 = wp[1];
        u64 h0 = pack2(a4.x, a4.x), h1 = pack2(a4.y, a4.y);
        u64 h2 = pack2(a4.z, a4.z), h3 = pack2(a4.w, a4.w);
        fma2(acc[0][0], h0, w0); fma2(acc[0][1], h0, w1);
        fma2(acc[1][0], h1, w0); fma2(acc[1][1], h1, w1);
        fma2(acc[2][0], h2, w0); fma2(acc[2][1], h2, w1);
        fma2(acc[3][0], h3, w0); fma2(acc[3][1], h3, w1);
    }

    float4* kvout = g_kv4 + ((size_t)(tok0 + tg * 4) * NHEADS + head) * 8 + jg;
#pragma unroll
    for (int t = 0; t < 4; t++) {
        float2 lo = unpack2(acc[t][0]);
        float2 hi = unpack2(acc[t][1]);
        kvout[t * 128] = make_float4(lo.x, lo.y, hi.x, hi.y);
    }
}

// ---------------------------------------------------------------------------
// Kernel 3 (FUSED): stack update + gate softmax + mem + up-projection + out.
// Block = one token x 4 heads (4 warps). Neighbor stack values via register
// shuffles (send-rotation) instead of L1-hit reloads — removes 8 LDG.128/thr
// from the binding L1TEX pipe. Up-projection: repartitioned broadcast scheme
// with conflict-free transposed Wu fill (R14).
// ---------------------------------------------------------------------------
__global__ __launch_bounds__(128, 7) void k_stack_out(
    const float* __restrict__ hidden,
    const float* __restrict__ stack,
    const float* __restrict__ mask,
    const float* __restrict__ Wg,
    const float* __restrict__ bg,
    const float* __restrict__ Wu,
    const float* __restrict__ bu,
    const float* __restrict__ res_w,
    float* __restrict__ out,
    float* __restrict__ new_stack,
    float* __restrict__ new_mask)
{
    __shared__ __align__(16) u64    sWuT[32 * 34];  // 8.5 KB: WuT[p][sd], pad 2
    __shared__ __align__(16) float4 sMem[4][9];     // padded rows

    const int tid  = threadIdx.x;
    const int wl   = tid >> 5;
    const int lane = tid & 31;
    const int g    = lane >> 3;
    const int c    = lane & 7;

    // ---- conflict-free WuT fill ----
    {
        const u64* Wu2 = (const u64*)Wu;
#pragma unroll
        for (int k = 0; k < 2; k++) {
            const int sd0 = wl * 8 + k * 4;
            u64 w0 = __ldg(&Wu2[(size_t)(sd0 + 0) * 32 + lane]);  // coalesced 256B
            u64 w1 = __ldg(&Wu2[(size_t)(sd0 + 1) * 32 + lane]);
            u64 w2 = __ldg(&Wu2[(size_t)(sd0 + 2) * 32 + lane]);
            u64 w3 = __ldg(&Wu2[(size_t)(sd0 + 3) * 32 + lane]);
            ulonglong2 a; a.x = w0; a.y = w1;
            ulonglong2 b; b.x = w2; b.y = w3;
            *(ulonglong2*)&sWuT[lane * 34 + sd0]     = a;   // STS.128, CF
            *(ulonglong2*)&sWuT[lane * 34 + sd0 + 2] = b;
        }
    }
    __syncthreads();

    const size_t th = (size_t)blockIdx.x * 4 + wl;
    const float4* stk4 = (const float4*)stack + th * 128;

    float4 st[4];
#pragma unroll
    for (int i = 0; i < 4; i++) st[i] = __ldcs(&stk4[i * 32 + lane]);

    const float4 kv4 = __ldg(&g_kv4[th * 8 + c]);
    const float4 act = __ldg(&g_act4[th]);
    const float a_push = act.x, a_pop = act.y, a_noop = act.z;
    const float4 wg4 = __ldg(&((const float4*)Wg)[c]);

    float q[4];
#pragma unroll
    for (int i = 0; i < 4; i++) {
        q[i] = dot4(st[i], wg4);
        q[i] += __shfl_xor_sync(FULLMASK, q[i], 1);
        q[i] += __shfl_xor_sync(FULLMASK, q[i], 2);
        q[i] += __shfl_xor_sync(FULLMASK, q[i], 4);
    }
    float qk = dot4(kv4, wg4);
    qk += __shfl_xor_sync(FULLMASK, qk, 1);
    qk += __shfl_xor_sync(FULLMASK, qk, 2);
    qk += __shfl_xor_sync(FULLMASK, qk, 4);

    float qn[4], qp[4];
#pragma unroll
    for (int i = 0; i < 4; i++) {
        float sn = (g == 0) ? ((i < 3) ? q[i + 1] : 0.f) : q[i];
        qn[i] = __shfl_sync(FULLMASK, sn, (lane + 8) & 31);
        float sp = (g == 3) ? ((i > 0) ? q[i - 1] : 0.f) : q[i];
        qp[i] = __shfl_sync(FULLMASK, sp, (lane + 24) & 31);
    }
    if (g == 0) qp[0] = qk;

    const float bgv = __ldg(&bg[0]);
    const float* mk = mask + th * SLOTS;
    float nm[4], e[4];
    float mx = -3.4e38f;
#pragma unroll
    for (int i = 0; i < 4; i++) {
        const int slot = i * 4 + g;
        float m  = __ldcs(&mk[slot]);
        float mn = (slot < 15) ? __ldcs(&mk[slot + 1]) : 0.f;
        float mp = (slot > 0)  ? __ldcs(&mk[slot - 1]) : 1.f;
        nm[i] = fmaf(a_push, mp, fmaf(a_pop, mn, a_noop * m));
        float sc = fmaf(a_push, qp[i], fmaf(a_pop, qn[i], a_noop * q[i])) + bgv;
        sc += (1.f - nm[i]) * (-1e9f);
        e[i] = sc;
        mx = fmaxf(mx, sc);
    }
    mx = fmaxf(mx, __shfl_xor_sync(FULLMASK, mx, 8));
    mx = fmaxf(mx, __shfl_xor_sync(FULLMASK, mx, 16));
    float ssum = 0.f;
#pragma unroll
    for (int i = 0; i < 4; i++) { e[i] = __expf(e[i] - mx); ssum += e[i]; }
    ssum += __shfl_xor_sync(FULLMASK, ssum, 8);
    ssum += __shfl_xor_sync(FULLMASK, ssum, 16);
    const float ginv = 1.f / ssum;

    if (c == 0) {
#pragma unroll
        for (int i = 0; i < 4; i++)
            __stcs(&new_mask[th * SLOTS + i * 4 + g], nm[i]);
    }

    // ---- new_stack: neighbors via register shuffles (no L1 reloads)
    float4* nst4 = (float4*)new_stack + th * 128;
    float4 acc = f4zero();
#pragma unroll
    for (int i = 0; i < 4; i++) {
        // nx = stack[slot+1]: send st[i] (g<3 receivers) / st[i+1] (g==3 recv)
        float4 sv = (g == 0) ? ((i < 3) ? st[i + 1] : f4zero()) : st[i];
        float4 nx = f4shfl(sv, (lane + 8) & 31);
        // pv = stack[slot-1]: send st[i] (g>0 recv) / st[i-1] (g==0 recv)
        float4 sp = (g == 3) ? ((i > 0) ? st[i - 1] : f4zero()) : st[i];
        float4 pv = f4shfl(sp, (lane + 24) & 31);
        if (g == 0 && i == 0) pv = kv4;

        float4 ns;
        ns.x = fmaf(a_push, pv.x, fmaf(a_pop, nx.x, a_noop * st[i].x));
        ns.y = fmaf(a_push, pv.y, fmaf(a_pop, nx.y, a_noop * st[i].y));
        ns.z = fmaf(a_push, pv.z, fmaf(a_pop, nx.z, a_noop * st[i].z));
        ns.w = fmaf(a_push, pv.w, fmaf(a_pop, nx.w, a_noop * st[i].w));
        __stcs(&nst4[i * 32 + lane], ns);
        acc = f4fma(e[i] * ginv, ns, acc);
    }
    acc = f4add(acc, f4shflxor(acc, 8));
    acc = f4add(acc, f4shflxor(acc, 16));
    if (g == 0) sMem[wl][c] = acc;      // mem[4c..4c+3] of head wl
    __syncthreads();

    // ---- up-projection, block-wide repartition (broadcast-shared weights)
    const int hh = lane & 3;
    const int p  = wl * 8 + (lane >> 2);
    u64 oacc = __ldg(&((const u64*)bu)[p]);
    const u64* wrow = &sWuT[p * 34];
    const float* memf = (const float*)&sMem[hh][0];
#pragma unroll
    for (int s4 = 0; s4 < 8; s4++) {
        float4 m4 = *(const float4*)&memf[s4 * 4];              // bcast LDS.128
        ulonglong2 wab = *(const ulonglong2*)&wrow[s4 * 4];     // bcast LDS.128
        ulonglong2 wcd = *(const ulonglong2*)&wrow[s4 * 4 + 2];
        fma2(oacc, pack2(m4.x, m4.x), wab.x);
        fma2(oacc, pack2(m4.y, m4.y), wab.y);
        fma2(oacc, pack2(m4.z, m4.z), wcd.x);
        fma2(oacc, pack2(m4.w, m4.w), wcd.y);
    }

    const float rw = __ldg(&res_w[0]);
    const int token = blockIdx.x >> 2;
    const int head  = (blockIdx.x & 3) * 4 + hh;
    const size_t obase = (size_t)token * HDIM + head * HD + 2 * p;
    float2 hv = __ldcs((const float2*)&hidden[obase]);
    float2 ov = unpack2(oacc);
    float2 res;
    res.x = fmaf(ov.x, rw, hv.x);
    res.y = fmaf(ov.y, rw, hv.y);
    __stcs((float2*)&out[obase], res);
}

// ---------------------------------------------------------------------------
extern "C" void kernel_launch(void* const* d_in, const int* in_sizes, int n_in,
                              void* d_out, int out_size)
{
    const float* hidden = (const float*)d_in[0];
    const float* stack  = (const float*)d_in[1];
    const float* mask   = (const float*)d_in[2];
    const float* Wa     = (const float*)d_in[3];
    const float* ba     = (const float*)d_in[4];
    const float* Wd     = (const float*)d_in[5];
    const float* bd     = (const float*)d_in[6];
    const float* Wu     = (const float*)d_in[7];
    const float* bu     = (const float*)d_in[8];
    const float* Wg     = (const float*)d_in[9];
    const float* bg     = (const float*)d_in[10];
    const float* res_w  = (const float*)d_in[11];

    float* out       = (float*)d_out;
    float* new_stack = out + (size_t)N_TOKENS * HDIM;
    float* new_mask  = new_stack + (size_t)N_TOKENS * NHEADS * SLOTS * SD;

    (void)in_sizes; (void)n_in; (void)out_size;

    k_waT<<<192, 256>>>(Wa);
    k_actions_part<<<256, 256>>>(hidden);
    k_kv<<<(N_TOKENS / 128) * NHEADS, 256>>>(hidden, Wd, bd, ba);
    k_stack_out<<<N_TOKENS * NHEADS / 4, 128>>>(hidden, stack, mask, Wg, bg,
                                                Wu, bu, res_w,
                                                out, new_stack, new_mask);
}

// round 16
// speedup vs baseline: 1.1732x; 1.0698x over previous
#include <cuda_runtime.h>
#include <cstdint>
#include <cstddef>

#define N_TOKENS 8192
#define HDIM     1024
#define NHEADS   16
#define SLOTS    16
#define SD       32
#define HD       64
#define FULLMASK 0xffffffffu

typedef unsigned long long u64;

__device__ float4 g_act4[N_TOKENS * NHEADS];
__device__ float  g_WaT[48 * HDIM];                      // WaT[col][k]
__device__ float  g_part[4 * N_TOKENS * 48];             // k-split partials
__device__ float4 g_kv4[(size_t)N_TOKENS * NHEADS * 8];  // kv [tok][head][32]

// ---------------------- helpers ----------------------
__device__ __forceinline__ u64 pack2(float x, float y) {
    u64 r; asm("mov.b64 %0,{%1,%2};" : "=l"(r) : "f"(x), "f"(y)); return r;
}
__device__ __forceinline__ void fma2(u64& d, u64 a, u64 b) {
    asm("fma.rn.f32x2 %0,%1,%2,%0;" : "+l"(d) : "l"(a), "l"(b));
}
__device__ __forceinline__ float2 unpack2(u64 v) {
    float2 r; asm("mov.b64 {%0,%1},%2;" : "=f"(r.x), "=f"(r.y) : "l"(v)); return r;
}
__device__ __forceinline__ float4 f4zero() { return make_float4(0.f, 0.f, 0.f, 0.f); }
__device__ __forceinline__ float4 f4fma(float a, float4 b, float4 c) {
    return make_float4(fmaf(a, b.x, c.x), fmaf(a, b.y, c.y),
                       fmaf(a, b.z, c.z), fmaf(a, b.w, c.w));
}
__device__ __forceinline__ float4 f4add(float4 a, float4 b) {
    return make_float4(a.x + b.x, a.y + b.y, a.z + b.z, a.w + b.w);
}
__device__ __forceinline__ float dot4(float4 a, float4 b) {
    return fmaf(a.x, b.x, fmaf(a.y, b.y, fmaf(a.z, b.z, a.w * b.w)));
}
__device__ __forceinline__ float4 f4shflxor(float4 v, int m) {
    return make_float4(__shfl_xor_sync(FULLMASK, v.x, m),
                       __shfl_xor_sync(FULLMASK, v.y, m),
                       __shfl_xor_sync(FULLMASK, v.z, m),
                       __shfl_xor_sync(FULLMASK, v.w, m));
}
__device__ __forceinline__ float4 f4shfl(float4 v, int src) {
    return make_float4(__shfl_sync(FULLMASK, v.x, src),
                       __shfl_sync(FULLMASK, v.y, src),
                       __shfl_sync(FULLMASK, v.z, src),
                       __shfl_sync(FULLMASK, v.w, src));
}

// ---------------------------------------------------------------------------
// Kernel 0: transpose Wa [1024][48] -> g_WaT [48][1024]
// ---------------------------------------------------------------------------
__global__ __launch_bounds__(256) void k_waT(const float* __restrict__ Wa)
{
    const int col = blockIdx.x >> 2;
    const int k   = (blockIdx.x & 3) * 256 + threadIdx.x;
    g_WaT[col * HDIM + k] = Wa[(size_t)k * 48 + col];
}

// ---------------------------------------------------------------------------
// Kernel 1: partial logits GEMM. Block = 128 tok x 48 col x 256-k chunk.
// ---------------------------------------------------------------------------
__global__ __launch_bounds__(256) void k_actions_part(
    const float* __restrict__ hidden)
{
    __shared__ __align__(16) float sA[128][68];
    __shared__ __align__(16) float sWT[48][68];

    const int tid  = threadIdx.x;
    const int ty   = tid >> 3;
    const int tx   = tid & 7;
    const int tile = blockIdx.x >> 2;
    const int kc   = blockIdx.x & 3;
    const int tok0 = tile * 128;
    const float4* hid4 = (const float4*)hidden;
    const float4* waT4 = (const float4*)g_WaT;

    u64 acc[4][6];
#pragma unroll
    for (int t = 0; t < 4; t++)
#pragma unroll
        for (int j = 0; j < 6; j++) acc[t][j] = 0ull;

#pragma unroll
    for (int sub = 0; sub < 4; sub++) {
        const int k4 = kc * 64 + sub * 16;
#pragma unroll
        for (int idx = tid; idx < 2048; idx += 256) {
            int r = idx >> 4, c4 = idx & 15;
            *(float4*)&sA[r][c4 * 4] = hid4[(size_t)(tok0 + r) * 256 + k4 + c4];
        }
#pragma unroll
        for (int idx = tid; idx < 768; idx += 256) {
            int r = idx >> 4, c4 = idx & 15;
            *(float4*)&sWT[r][c4 * 4] = waT4[(size_t)r * 256 + k4 + c4];
        }
        __syncthreads();

#pragma unroll 8
        for (int k2 = 0; k2 < 32; k2++) {
            u64 a[4];
#pragma unroll
            for (int t = 0; t < 4; t++)
                a[t] = *(const u64*)&sA[ty * 4 + t][k2 * 2];
#pragma unroll
            for (int j = 0; j < 6; j++) {
                u64 w = *(const u64*)&sWT[tx * 6 + j][k2 * 2];
                fma2(acc[0][j], a[0], w);
                fma2(acc[1][j], a[1], w);
                fma2(acc[2][j], a[2], w);
                fma2(acc[3][j], a[3], w);
            }
        }
        __syncthreads();
    }

#pragma unroll
    for (int t = 0; t < 4; t++) {
        const size_t base = ((size_t)kc * N_TOKENS + tok0 + ty * 4 + t) * 48 + tx * 6;
#pragma unroll
        for (int j2 = 0; j2 < 3; j2++) {
            float2 pa = unpack2(acc[t][j2 * 2]);
            float2 pb = unpack2(acc[t][j2 * 2 + 1]);
            *(float2*)&g_part[base + j2 * 2] = make_float2(pa.x + pa.y, pb.x + pb.y);
        }
    }
}

// ---------------------------------------------------------------------------
// Kernel 2: kv = hidden-slice @ Wd + bd (block = 128 tok x 1 head, 256 thr),
// absorbed action reduce. Swizzle at d>>2 granularity: fill stores 2-way max
// (banks 4*(tq^c4)+tr), reads stay conflict-free broadcast.
// ---------------------------------------------------------------------------
__global__ __launch_bounds__(256) void k_kv(
    const float* __restrict__ hidden,
    const float* __restrict__ Wd,
    const float* __restrict__ bd,
    const float* __restrict__ ba)
{
    __shared__ __align__(16) float sAT[64 * 128];   // 32 KB
    __shared__ __align__(16) u64   sWd2[64 * 16];   // 8 KB [d][pair]

    const int tid  = threadIdx.x;
    const int head = blockIdx.x & 15;
    const int tok0 = (blockIdx.x >> 4) * 128;
    const int jg   = tid & 7;
    const int tg   = tid >> 3;

    ((float4*)sWd2)[tid]       = ((const float4*)Wd)[tid];
    ((float4*)sWd2)[tid + 256] = ((const float4*)Wd)[tid + 256];

    // absorbed action reduce: thread t < 128 handles token tok0+t, this head
    if (tid < 128) {
        const int token = tok0 + tid;
        float l[3];
#pragma unroll
        for (int j = 0; j < 3; j++) {
            const size_t col = (size_t)token * 48 + head * 3 + j;
            float s = g_part[col]
                    + g_part[(size_t)N_TOKENS * 48 + col]
                    + g_part[(size_t)2 * N_TOKENS * 48 + col]
                    + g_part[(size_t)3 * N_TOKENS * 48 + col];
            l[j] = (s + __ldg(&ba[head * 3 + j])) * 0.125f;
        }
        float mx = fmaxf(l[0], fmaxf(l[1], l[2]));
        float e0 = __expf(l[0] - mx);
        float e1 = __expf(l[1] - mx);
        float e2 = __expf(l[2] - mx);
        float inv = 1.f / (e0 + e1 + e2);
        g_act4[(size_t)token * NHEADS + head] =
            make_float4(e0 * inv, e1 * inv, e2 * inv, 0.f);
    }

    const float4* hid4 = (const float4*)hidden;
#pragma unroll
    for (int k = 0; k < 8; k++) {
        int idx = k * 256 + tid;
        int tok = idx >> 4, c4 = idx & 15;
        float4 v = __ldcs(&hid4[(size_t)(tok0 + tok) * 256 + head * 16 + c4]);
        const int tq = tok >> 2, tr = tok & 3;
        const int col4 = (tq ^ c4) << 2;        // d>>2 == c4 for all 4 scalars
        const int d0 = c4 * 4;
        sAT[(d0 + 0) * 128 + col4 + tr] = v.x;
        sAT[(d0 + 1) * 128 + col4 + tr] = v.y;
        sAT[(d0 + 2) * 128 + col4 + tr] = v.z;
        sAT[(d0 + 3) * 128 + col4 + tr] = v.w;
    }
    __syncthreads();

    u64 acc[4][2];
    {
        const u64* bd2 = (const u64*)bd;
        u64 b0 = __ldg(&bd2[jg * 2]);
        u64 b1 = __ldg(&bd2[jg * 2 + 1]);
#pragma unroll
        for (int t = 0; t < 4; t++) { acc[t][0] = b0; acc[t][1] = b1; }
    }

#pragma unroll 16
    for (int d = 0; d < HD; d++) {
        float4 a4 = *(const float4*)&sAT[d * 128 + ((tg ^ (d >> 2)) << 2)];
        const u64* wp = &sWd2[d * 16 + jg * 2];
        u64 w0 = wp[0], w1 = wp[1];
        u64 h0 = pack2(a4.x, a4.x), h1 = pack2(a4.y, a4.y);
        u64 h2 = pack2(a4.z, a4.z), h3 = pack2(a4.w, a4.w);
        fma2(acc[0][0], h0, w0); fma2(acc[0][1], h0, w1);
        fma2(acc[1][0], h1, w0); fma2(acc[1][1], h1, w1);
        fma2(acc[2][0], h2, w0); fma2(acc[2][1], h2, w1);
        fma2(acc[3][0], h3, w0); fma2(acc[3][1], h3, w1);
    }

    float4* kvout = g_kv4 + ((size_t)(tok0 + tg * 4) * NHEADS + head) * 8 + jg;
#pragma unroll
    for (int t = 0; t < 4; t++) {
        float2 lo = unpack2(acc[t][0]);
        float2 hi = unpack2(acc[t][1]);
        kvout[t * 128] = make_float4(lo.x, lo.y, hi.x, hi.y);
    }
}

// ---------------------------------------------------------------------------
// Kernel 3 (FUSED): stack update + gate softmax + mem + up-projection + out.
// Block = 2 tokens x 4 heads (4 warps, looped): Wu fill amortized over 2
// tokens; masks + stack neighbors via register shuffles; double-buffered sMem.
// ---------------------------------------------------------------------------
__global__ __launch_bounds__(128, 7) void k_stack_out(
    const float* __restrict__ hidden,
    const float* __restrict__ stack,
    const float* __restrict__ mask,
    const float* __restrict__ Wg,
    const float* __restrict__ bg,
    const float* __restrict__ Wu,
    const float* __restrict__ bu,
    const float* __restrict__ res_w,
    float* __restrict__ out,
    float* __restrict__ new_stack,
    float* __restrict__ new_mask)
{
    __shared__ __align__(16) u64    sWuT[32 * 34];  // 8.5 KB: WuT[p][sd], pad 2
    __shared__ __align__(16) float4 sMem[2][4][9];  // double-buffered

    const int tid  = threadIdx.x;
    const int wl   = tid >> 5;
    const int lane = tid & 31;
    const int g    = lane >> 3;
    const int c    = lane & 7;

    // ---- conflict-free WuT fill (once per block) ----
    {
        const u64* Wu2 = (const u64*)Wu;
#pragma unroll
        for (int k = 0; k < 2; k++) {
            const int sd0 = wl * 8 + k * 4;
            u64 w0 = __ldg(&Wu2[(size_t)(sd0 + 0) * 32 + lane]);
            u64 w1 = __ldg(&Wu2[(size_t)(sd0 + 1) * 32 + lane]);
            u64 w2 = __ldg(&Wu2[(size_t)(sd0 + 2) * 32 + lane]);
            u64 w3 = __ldg(&Wu2[(size_t)(sd0 + 3) * 32 + lane]);
            ulonglong2 a; a.x = w0; a.y = w1;
            ulonglong2 b; b.x = w2; b.y = w3;
            *(ulonglong2*)&sWuT[lane * 34 + sd0]     = a;
            *(ulonglong2*)&sWuT[lane * 34 + sd0 + 2] = b;
        }
    }
    __syncthreads();

    // loop-invariant loads
    const float4 wg4 = __ldg(&((const float4*)Wg)[c]);
    const float bgv  = __ldg(&bg[0]);
    const float rw   = __ldg(&res_w[0]);
    const int hh = lane & 3;
    const int p  = wl * 8 + (lane >> 2);
    const u64 bup = __ldg(&((const u64*)bu)[p]);
    const u64* wrow = &sWuT[p * 34];

    const int hb   = blockIdx.x & 3;      // head group
    const int tokp = blockIdx.x >> 2;     // token pair

#pragma unroll
    for (int t = 0; t < 2; t++) {
        const int token = tokp * 2 + t;
        const size_t th = (size_t)token * NHEADS + hb * 4 + wl;
        const float4* stk4 = (const float4*)stack + th * 128;

        float4 st[4];
#pragma unroll
        for (int i = 0; i < 4; i++) st[i] = __ldcs(&stk4[i * 32 + lane]);

        const float4 kv4 = __ldg(&g_kv4[th * 8 + c]);
        const float4 act = __ldg(&g_act4[th]);
        const float a_push = act.x, a_pop = act.y, a_noop = act.z;

        float q[4];
#pragma unroll
        for (int i = 0; i < 4; i++) {
            q[i] = dot4(st[i], wg4);
            q[i] += __shfl_xor_sync(FULLMASK, q[i], 1);
            q[i] += __shfl_xor_sync(FULLMASK, q[i], 2);
            q[i] += __shfl_xor_sync(FULLMASK, q[i], 4);
        }
        float qk = dot4(kv4, wg4);
        qk += __shfl_xor_sync(FULLMASK, qk, 1);
        qk += __shfl_xor_sync(FULLMASK, qk, 2);
        qk += __shfl_xor_sync(FULLMASK, qk, 4);

        // masks: 4 LDG (owned slots), neighbors via send-rotation shuffles
        const float* mk = mask + th * SLOTS;
        float m[4];
#pragma unroll
        for (int i = 0; i < 4; i++) m[i] = __ldcs(&mk[i * 4 + g]);

        float nm[4], e[4];
        float mx = -3.4e38f;
#pragma unroll
        for (int i = 0; i < 4; i++) {
            float sq = (g == 0) ? ((i < 3) ? q[i + 1] : 0.f) : q[i];
            float sm = (g == 0) ? ((i < 3) ? m[i + 1] : 0.f) : m[i];
            float qn = __shfl_sync(FULLMASK, sq, (lane + 8) & 31);
            float mn = __shfl_sync(FULLMASK, sm, (lane + 8) & 31);
            float pq = (g == 3) ? ((i > 0) ? q[i - 1] : 0.f) : q[i];
            float pm = (g == 3) ? ((i > 0) ? m[i - 1] : 0.f) : m[i];
            float qp = __shfl_sync(FULLMASK, pq, (lane + 24) & 31);
            float mp = __shfl_sync(FULLMASK, pm, (lane + 24) & 31);
            if (g == 0 && i == 0) { qp = qk; mp = 1.f; }

            nm[i] = fmaf(a_push, mp, fmaf(a_pop, mn, a_noop * m[i]));
            float sc = fmaf(a_push, qp, fmaf(a_pop, qn, a_noop * q[i])) + bgv;
            sc += (1.f - nm[i]) * (-1e9f);
            e[i] = sc;
            mx = fmaxf(mx, sc);
        }
        mx = fmaxf(mx, __shfl_xor_sync(FULLMASK, mx, 8));
        mx = fmaxf(mx, __shfl_xor_sync(FULLMASK, mx, 16));
        float ssum = 0.f;
#pragma unroll
        for (int i = 0; i < 4; i++) { e[i] = __expf(e[i] - mx); ssum += e[i]; }
        ssum += __shfl_xor_sync(FULLMASK, ssum, 8);
        ssum += __shfl_xor_sync(FULLMASK, ssum, 16);
        const float ginv = 1.f / ssum;

        if (c == 0) {
#pragma unroll
            for (int i = 0; i < 4; i++)
                __stcs(&new_mask[th * SLOTS + i * 4 + g], nm[i]);
        }

        // new_stack: neighbors via register shuffles
        float4* nst4 = (float4*)new_stack + th * 128;
        float4 acc = f4zero();
#pragma unroll
        for (int i = 0; i < 4; i++) {
            float4 sv = (g == 0) ? ((i < 3) ? st[i + 1] : f4zero()) : st[i];
            float4 nx = f4shfl(sv, (lane + 8) & 31);
            float4 sp = (g == 3) ? ((i > 0) ? st[i - 1] : f4zero()) : st[i];
            float4 pv = f4shfl(sp, (lane + 24) & 31);
            if (g == 0 && i == 0) pv = kv4;

            float4 ns;
            ns.x = fmaf(a_push, pv.x, fmaf(a_pop, nx.x, a_noop * st[i].x));
            ns.y = fmaf(a_push, pv.y, fmaf(a_pop, nx.y, a_noop * st[i].y));
            ns.z = fmaf(a_push, pv.z, fmaf(a_pop, nx.z, a_noop * st[i].z));
            ns.w = fmaf(a_push, pv.w, fmaf(a_pop, nx.w, a_noop * st[i].w));
            __stcs(&nst4[i * 32 + lane], ns);
            acc = f4fma(e[i] * ginv, ns, acc);
        }
        acc = f4add(acc, f4shflxor(acc, 8));
        acc = f4add(acc, f4shflxor(acc, 16));
        if (g == 0) sMem[t][wl][c] = acc;
        __syncthreads();

        // up-projection, block-wide repartition (broadcast-shared weights)
        u64 oacc = bup;
        const float* memf = (const float*)&sMem[t][hh][0];
#pragma unroll
        for (int s4 = 0; s4 < 8; s4++) {
            float4 m4 = *(const float4*)&memf[s4 * 4];
            ulonglong2 wab = *(const ulonglong2*)&wrow[s4 * 4];
            ulonglong2 wcd = *(const ulonglong2*)&wrow[s4 * 4 + 2];
            fma2(oacc, pack2(m4.x, m4.x), wab.x);
            fma2(oacc, pack2(m4.y, m4.y), wab.y);
            fma2(oacc, pack2(m4.z, m4.z), wcd.x);
            fma2(oacc, pack2(m4.w, m4.w), wcd.y);
        }

        const int head = hb * 4 + hh;
        const size_t obase = (size_t)token * HDIM + head * HD + 2 * p;
        float2 hv = __ldcs((const float2*)&hidden[obase]);
        float2 ov = unpack2(oacc);
        float2 res;
        res.x = fmaf(ov.x, rw, hv.x);
        res.y = fmaf(ov.y, rw, hv.y);
        __stcs((float2*)&out[obase], res);
    }
}

// ---------------------------------------------------------------------------
extern "C" void kernel_launch(void* const* d_in, const int* in_sizes, int n_in,
                              void* d_out, int out_size)
{
    const float* hidden = (const float*)d_in[0];
    const float* stack  = (const float*)d_in[1];
    const float* mask   = (const float*)d_in[2];
    const float* Wa     = (const float*)d_in[3];
    const float* ba     = (const float*)d_in[4];
    const float* Wd     = (const float*)d_in[5];
    const float* bd     = (const float*)d_in[6];
    const float* Wu     = (const float*)d_in[7];
    const float* bu     = (const float*)d_in[8];
    const float* Wg     = (const float*)d_in[9];
    const float* bg     = (const float*)d_in[10];
    const float* res_w  = (const float*)d_in[11];

    float* out       = (float*)d_out;
    float* new_stack = out + (size_t)N_TOKENS * HDIM;
    float* new_mask  = new_stack + (size_t)N_TOKENS * NHEADS * SLOTS * SD;

    (void)in_sizes; (void)n_in; (void)out_size;

    k_waT<<<192, 256>>>(Wa);
    k_actions_part<<<256, 256>>>(hidden);
    k_kv<<<(N_TOKENS / 128) * NHEADS, 256>>>(hidden, Wd, bd, ba);
    k_stack_out<<<(N_TOKENS / 2) * 4, 128>>>(hidden, stack, mask, Wg, bg,
                                             Wu, bu, res_w,
                                             out, new_stack, new_mask);
}

// round 17
// speedup vs baseline: 1.1867x; 1.0115x over previous
#include <cuda_runtime.h>
#include <cstdint>
#include <cstddef>

#define N_TOKENS 8192
#define HDIM     1024
#define NHEADS   16
#define SLOTS    16
#define SD       32
#define HD       64
#define FULLMASK 0xffffffffu

typedef unsigned long long u64;

__device__ float4 g_act4[N_TOKENS * NHEADS];
__device__ float  g_WaT[48 * HDIM];                      // WaT[col][k]
__device__ float  g_part[4 * N_TOKENS * 48];             // k-split partials
__device__ float4 g_kv4[(size_t)N_TOKENS * NHEADS * 8];  // kv [tok][head][32]

// ---------------------- helpers ----------------------
__device__ __forceinline__ u64 pack2(float x, float y) {
    u64 r; asm("mov.b64 %0,{%1,%2};" : "=l"(r) : "f"(x), "f"(y)); return r;
}
__device__ __forceinline__ void fma2(u64& d, u64 a, u64 b) {
    asm("fma.rn.f32x2 %0,%1,%2,%0;" : "+l"(d) : "l"(a), "l"(b));
}
__device__ __forceinline__ float2 unpack2(u64 v) {
    float2 r; asm("mov.b64 {%0,%1},%2;" : "=f"(r.x), "=f"(r.y) : "l"(v)); return r;
}
__device__ __forceinline__ float4 f4zero() { return make_float4(0.f, 0.f, 0.f, 0.f); }
__device__ __forceinline__ float4 f4fma(float a, float4 b, float4 c) {
    return make_float4(fmaf(a, b.x, c.x), fmaf(a, b.y, c.y),
                       fmaf(a, b.z, c.z), fmaf(a, b.w, c.w));
}
__device__ __forceinline__ float4 f4add(float4 a, float4 b) {
    return make_float4(a.x + b.x, a.y + b.y, a.z + b.z, a.w + b.w);
}
__device__ __forceinline__ float dot4(float4 a, float4 b) {
    return fmaf(a.x, b.x, fmaf(a.y, b.y, fmaf(a.z, b.z, a.w * b.w)));
}
__device__ __forceinline__ float4 f4shflxor(float4 v, int m) {
    return make_float4(__shfl_xor_sync(FULLMASK, v.x, m),
                       __shfl_xor_sync(FULLMASK, v.y, m),
                       __shfl_xor_sync(FULLMASK, v.z, m),
                       __shfl_xor_sync(FULLMASK, v.w, m));
}
__device__ __forceinline__ float4 f4shfl(float4 v, int src) {
    return make_float4(__shfl_sync(FULLMASK, v.x, src),
                       __shfl_sync(FULLMASK, v.y, src),
                       __shfl_sync(FULLMASK, v.z, src),
                       __shfl_sync(FULLMASK, v.w, src));
}

// ---------------------------------------------------------------------------
// Kernel 0: transpose Wa [1024][48] -> g_WaT [48][1024]
// ---------------------------------------------------------------------------
__global__ __launch_bounds__(256) void k_waT(const float* __restrict__ Wa)
{
    const int col = blockIdx.x >> 2;
    const int k   = (blockIdx.x & 3) * 256 + threadIdx.x;
    g_WaT[col * HDIM + k] = Wa[(size_t)k * 48 + col];
}

// ---------------------------------------------------------------------------
// Kernel 1: partial logits GEMM. Block = 128 tok x 48 col x 256-k chunk.
// ---------------------------------------------------------------------------
__global__ __launch_bounds__(256) void k_actions_part(
    const float* __restrict__ hidden)
{
    __shared__ __align__(16) float sA[128][68];
    __shared__ __align__(16) float sWT[48][68];

    const int tid  = threadIdx.x;
    const int ty   = tid >> 3;
    const int tx   = tid & 7;
    const int tile = blockIdx.x >> 2;
    const int kc   = blockIdx.x & 3;
    const int tok0 = tile * 128;
    const float4* hid4 = (const float4*)hidden;
    const float4* waT4 = (const float4*)g_WaT;

    u64 acc[4][6];
#pragma unroll
    for (int t = 0; t < 4; t++)
#pragma unroll
        for (int j = 0; j < 6; j++) acc[t][j] = 0ull;

#pragma unroll
    for (int sub = 0; sub < 4; sub++) {
        const int k4 = kc * 64 + sub * 16;
#pragma unroll
        for (int idx = tid; idx < 2048; idx += 256) {
            int r = idx >> 4, c4 = idx & 15;
            *(float4*)&sA[r][c4 * 4] = hid4[(size_t)(tok0 + r) * 256 + k4 + c4];
        }
#pragma unroll
        for (int idx = tid; idx < 768; idx += 256) {
            int r = idx >> 4, c4 = idx & 15;
            *(float4*)&sWT[r][c4 * 4] = waT4[(size_t)r * 256 + k4 + c4];
        }
        __syncthreads();

#pragma unroll 8
        for (int k2 = 0; k2 < 32; k2++) {
            u64 a[4];
#pragma unroll
            for (int t = 0; t < 4; t++)
                a[t] = *(const u64*)&sA[ty * 4 + t][k2 * 2];
#pragma unroll
            for (int j = 0; j < 6; j++) {
                u64 w = *(const u64*)&sWT[tx * 6 + j][k2 * 2];
                fma2(acc[0][j], a[0], w);
                fma2(acc[1][j], a[1], w);
                fma2(acc[2][j], a[2], w);
                fma2(acc[3][j], a[3], w);
            }
        }
        __syncthreads();
    }

#pragma unroll
    for (int t = 0; t < 4; t++) {
        const size_t base = ((size_t)kc * N_TOKENS + tok0 + ty * 4 + t) * 48 + tx * 6;
#pragma unroll
        for (int j2 = 0; j2 < 3; j2++) {
            float2 pa = unpack2(acc[t][j2 * 2]);
            float2 pb = unpack2(acc[t][j2 * 2 + 1]);
            *(float2*)&g_part[base + j2 * 2] = make_float2(pa.x + pa.y, pb.x + pb.y);
        }
    }
}

// ---------------------------------------------------------------------------
// Kernel 2: kv = hidden-slice @ Wd + bd (block = 128 tok x 1 head, 256 thr),
// absorbed action reduce. Swizzle at d>>2 granularity.
// ---------------------------------------------------------------------------
__global__ __launch_bounds__(256) void k_kv(
    const float* __restrict__ hidden,
    const float* __restrict__ Wd,
    const float* __restrict__ bd,
    const float* __restrict__ ba)
{
    __shared__ __align__(16) float sAT[64 * 128];   // 32 KB
    __shared__ __align__(16) u64   sWd2[64 * 16];   // 8 KB [d][pair]

    const int tid  = threadIdx.x;
    const int head = blockIdx.x & 15;
    const int tok0 = (blockIdx.x >> 4) * 128;
    const int jg   = tid & 7;
    const int tg   = tid >> 3;

    ((float4*)sWd2)[tid]       = ((const float4*)Wd)[tid];
    ((float4*)sWd2)[tid + 256] = ((const float4*)Wd)[tid + 256];

    if (tid < 128) {
        const int token = tok0 + tid;
        float l[3];
#pragma unroll
        for (int j = 0; j < 3; j++) {
            const size_t col = (size_t)token * 48 + head * 3 + j;
            float s = g_part[col]
                    + g_part[(size_t)N_TOKENS * 48 + col]
                    + g_part[(size_t)2 * N_TOKENS * 48 + col]
                    + g_part[(size_t)3 * N_TOKENS * 48 + col];
            l[j] = (s + __ldg(&ba[head * 3 + j])) * 0.125f;
        }
        float mx = fmaxf(l[0], fmaxf(l[1], l[2]));
        float e0 = __expf(l[0] - mx);
        float e1 = __expf(l[1] - mx);
        float e2 = __expf(l[2] - mx);
        float inv = 1.f / (e0 + e1 + e2);
        g_act4[(size_t)token * NHEADS + head] =
            make_float4(e0 * inv, e1 * inv, e2 * inv, 0.f);
    }

    const float4* hid4 = (const float4*)hidden;
#pragma unroll
    for (int k = 0; k < 8; k++) {
        int idx = k * 256 + tid;
        int tok = idx >> 4, c4 = idx & 15;
        float4 v = __ldcs(&hid4[(size_t)(tok0 + tok) * 256 + head * 16 + c4]);
        const int tq = tok >> 2, tr = tok & 3;
        const int col4 = (tq ^ c4) << 2;
        const int d0 = c4 * 4;
        sAT[(d0 + 0) * 128 + col4 + tr] = v.x;
        sAT[(d0 + 1) * 128 + col4 + tr] = v.y;
        sAT[(d0 + 2) * 128 + col4 + tr] = v.z;
        sAT[(d0 + 3) * 128 + col4 + tr] = v.w;
    }
    __syncthreads();

    u64 acc[4][2];
    {
        const u64* bd2 = (const u64*)bd;
        u64 b0 = __ldg(&bd2[jg * 2]);
        u64 b1 = __ldg(&bd2[jg * 2 + 1]);
#pragma unroll
        for (int t = 0; t < 4; t++) { acc[t][0] = b0; acc[t][1] = b1; }
    }

#pragma unroll 16
    for (int d = 0; d < HD; d++) {
        float4 a4 = *(const float4*)&sAT[d * 128 + ((tg ^ (d >> 2)) << 2)];
        const u64* wp = &sWd2[d * 16 + jg * 2];
        u64 w0 = wp[0], w1 = wp[1];
        u64 h0 = pack2(a4.x, a4.x), h1 = pack2(a4.y, a4.y);
        u64 h2 = pack2(a4.z, a4.z), h3 = pack2(a4.w, a4.w);
        fma2(acc[0][0], h0, w0); fma2(acc[0][1], h0, w1);
        fma2(acc[1][0], h1, w0); fma2(acc[1][1], h1, w1);
        fma2(acc[2][0], h2, w0); fma2(acc[2][1], h2, w1);
        fma2(acc[3][0], h3, w0); fma2(acc[3][1], h3, w1);
    }

    float4* kvout = g_kv4 + ((size_t)(tok0 + tg * 4) * NHEADS + head) * 8 + jg;
#pragma unroll
    for (int t = 0; t < 4; t++) {
        float2 lo = unpack2(acc[t][0]);
        float2 hi = unpack2(acc[t][1]);
        kvout[t * 128] = make_float4(lo.x, lo.y, hi.x, hi.y);
    }
}

// ---------------------------------------------------------------------------
// Kernel 3 (FUSED): 4 tokens x 4 heads per block; pair-deferred up-projection
// shares the weight LDS pass between two tokens.
// ---------------------------------------------------------------------------
__global__ __launch_bounds__(128, 7) void k_stack_out(
    const float* __restrict__ hidden,
    const float* __restrict__ stack,
    const float* __restrict__ mask,
    const float* __restrict__ Wg,
    const float* __restrict__ bg,
    const float* __restrict__ Wu,
    const float* __restrict__ bu,
    const float* __restrict__ res_w,
    float* __restrict__ out,
    float* __restrict__ new_stack,
    float* __restrict__ new_mask)
{
    __shared__ __align__(16) u64    sWuT[32 * 34];  // 8.5 KB: WuT[p][sd], pad 2
    __shared__ __align__(16) float4 sMem[4][4][9];  // per-token buffers

    const int tid  = threadIdx.x;
    const int wl   = tid >> 5;
    const int lane = tid & 31;
    const int g    = lane >> 3;
    const int c    = lane & 7;

    // ---- conflict-free WuT fill (once per block, amortized over 4 tokens)
    {
        const u64* Wu2 = (const u64*)Wu;
#pragma unroll
        for (int k = 0; k < 2; k++) {
            const int sd0 = wl * 8 + k * 4;
            u64 w0 = __ldg(&Wu2[(size_t)(sd0 + 0) * 32 + lane]);
            u64 w1 = __ldg(&Wu2[(size_t)(sd0 + 1) * 32 + lane]);
            u64 w2 = __ldg(&Wu2[(size_t)(sd0 + 2) * 32 + lane]);
            u64 w3 = __ldg(&Wu2[(size_t)(sd0 + 3) * 32 + lane]);
            ulonglong2 a; a.x = w0; a.y = w1;
            ulonglong2 b; b.x = w2; b.y = w3;
            *(ulonglong2*)&sWuT[lane * 34 + sd0]     = a;
            *(ulonglong2*)&sWuT[lane * 34 + sd0 + 2] = b;
        }
    }
    __syncthreads();

    const float4 wg4 = __ldg(&((const float4*)Wg)[c]);
    const float bgv  = __ldg(&bg[0]);
    const float rw   = __ldg(&res_w[0]);
    const int hh = lane & 3;
    const int p  = wl * 8 + (lane >> 2);
    const u64 bup = __ldg(&((const u64*)bu)[p]);
    const u64* wrow = &sWuT[p * 34];

    const int hb   = blockIdx.x & 3;      // head group
    const int tokq = blockIdx.x >> 2;     // token quad

#pragma unroll
    for (int t = 0; t < 4; t++) {
        const int token = tokq * 4 + t;
        const size_t th = (size_t)token * NHEADS + hb * 4 + wl;
        const float4* stk4 = (const float4*)stack + th * 128;

        float4 st[4];
#pragma unroll
        for (int i = 0; i < 4; i++) st[i] = __ldcs(&stk4[i * 32 + lane]);

        const float4 kv4 = __ldg(&g_kv4[th * 8 + c]);
        const float4 act = __ldg(&g_act4[th]);
        const float a_push = act.x, a_pop = act.y, a_noop = act.z;

        float q[4];
#pragma unroll
        for (int i = 0; i < 4; i++) {
            q[i] = dot4(st[i], wg4);
            q[i] += __shfl_xor_sync(FULLMASK, q[i], 1);
            q[i] += __shfl_xor_sync(FULLMASK, q[i], 2);
            q[i] += __shfl_xor_sync(FULLMASK, q[i], 4);
        }
        float qk = dot4(kv4, wg4);
        qk += __shfl_xor_sync(FULLMASK, qk, 1);
        qk += __shfl_xor_sync(FULLMASK, qk, 2);
        qk += __shfl_xor_sync(FULLMASK, qk, 4);

        const float* mk = mask + th * SLOTS;
        float m[4];
#pragma unroll
        for (int i = 0; i < 4; i++) m[i] = __ldcs(&mk[i * 4 + g]);

        float nm[4], e[4];
        float mx = -3.4e38f;
#pragma unroll
        for (int i = 0; i < 4; i++) {
            float sq = (g == 0) ? ((i < 3) ? q[i + 1] : 0.f) : q[i];
            float sm = (g == 0) ? ((i < 3) ? m[i + 1] : 0.f) : m[i];
            float qn = __shfl_sync(FULLMASK, sq, (lane + 8) & 31);
            float mn = __shfl_sync(FULLMASK, sm, (lane + 8) & 31);
            float pq = (g == 3) ? ((i > 0) ? q[i - 1] : 0.f) : q[i];
            float pm = (g == 3) ? ((i > 0) ? m[i - 1] : 0.f) : m[i];
            float qp = __shfl_sync(FULLMASK, pq, (lane + 24) & 31);
            float mp = __shfl_sync(FULLMASK, pm, (lane + 24) & 31);
            if (g == 0 && i == 0) { qp = qk; mp = 1.f; }

            nm[i] = fmaf(a_push, mp, fmaf(a_pop, mn, a_noop * m[i]));
            float sc = fmaf(a_push, qp, fmaf(a_pop, qn, a_noop * q[i])) + bgv;
            sc += (1.f - nm[i]) * (-1e9f);
            e[i] = sc;
            mx = fmaxf(mx, sc);
        }
        mx = fmaxf(mx, __shfl_xor_sync(FULLMASK, mx, 8));
        mx = fmaxf(mx, __shfl_xor_sync(FULLMASK, mx, 16));
        float ssum = 0.f;
#pragma unroll
        for (int i = 0; i < 4; i++) { e[i] = __expf(e[i] - mx); ssum += e[i]; }
        ssum += __shfl_xor_sync(FULLMASK, ssum, 8);
        ssum += __shfl_xor_sync(FULLMASK, ssum, 16);
        const float ginv = 1.f / ssum;

        if (c == 0) {
#pragma unroll
            for (int i = 0; i < 4; i++)
                __stcs(&new_mask[th * SLOTS + i * 4 + g], nm[i]);
        }

        float4* nst4 = (float4*)new_stack + th * 128;
        float4 acc = f4zero();
#pragma unroll
        for (int i = 0; i < 4; i++) {
            float4 sv = (g == 0) ? ((i < 3) ? st[i + 1] : f4zero()) : st[i];
            float4 nx = f4shfl(sv, (lane + 8) & 31);
            float4 sp = (g == 3) ? ((i > 0) ? st[i - 1] : f4zero()) : st[i];
            float4 pv = f4shfl(sp, (lane + 24) & 31);
            if (g == 0 && i == 0) pv = kv4;

            float4 ns;
            ns.x = fmaf(a_push, pv.x, fmaf(a_pop, nx.x, a_noop * st[i].x));
            ns.y = fmaf(a_push, pv.y, fmaf(a_pop, nx.y, a_noop * st[i].y));
            ns.z = fmaf(a_push, pv.z, fmaf(a_pop, nx.z, a_noop * st[i].z));
            ns.w = fmaf(a_push, pv.w, fmaf(a_pop, nx.w, a_noop * st[i].w));
            __stcs(&nst4[i * 32 + lane], ns);
            acc = f4fma(e[i] * ginv, ns, acc);
        }
        acc = f4add(acc, f4shflxor(acc, 8));
        acc = f4add(acc, f4shflxor(acc, 16));
        if (g == 0) sMem[t][wl][c] = acc;
        __syncthreads();

        // ---- pair-deferred up-projection: after odd t, do tokens t-1 and t
        // sharing one weight-LDS pass.
        if (t & 1) {
            u64 oa = bup, ob = bup;
            const float* mfa = (const float*)&sMem[t - 1][hh][0];
            const float* mfb = (const float*)&sMem[t][hh][0];
#pragma unroll
            for (int s4 = 0; s4 < 8; s4++) {
                float4 ma = *(const float4*)&mfa[s4 * 4];
                float4 mb = *(const float4*)&mfb[s4 * 4];
                ulonglong2 wab = *(const ulonglong2*)&wrow[s4 * 4];
                ulonglong2 wcd = *(const ulonglong2*)&wrow[s4 * 4 + 2];
                fma2(oa, pack2(ma.x, ma.x), wab.x);
                fma2(ob, pack2(mb.x, mb.x), wab.x);
                fma2(oa, pack2(ma.y, ma.y), wab.y);
                fma2(ob, pack2(mb.y, mb.y), wab.y);
                fma2(oa, pack2(ma.z, ma.z), wcd.x);
                fma2(ob, pack2(mb.z, mb.z), wcd.x);
                fma2(oa, pack2(ma.w, ma.w), wcd.y);
                fma2(ob, pack2(mb.w, mb.w), wcd.y);
            }

            const int head = hb * 4 + hh;
#pragma unroll
            for (int u = 0; u < 2; u++) {
                const int tok = tokq * 4 + t - 1 + u;
                const size_t obase = (size_t)tok * HDIM + head * HD + 2 * p;
                float2 hv = __ldcs((const float2*)&hidden[obase]);
                float2 ov = unpack2(u == 0 ? oa : ob);
                float2 res;
                res.x = fmaf(ov.x, rw, hv.x);
                res.y = fmaf(ov.y, rw, hv.y);
                __stcs((float2*)&out[obase], res);
            }
        }
    }
}

// ---------------------------------------------------------------------------
extern "C" void kernel_launch(void* const* d_in, const int* in_sizes, int n_in,
                              void* d_out, int out_size)
{
    const float* hidden = (const float*)d_in[0];
    const float* stack  = (const float*)d_in[1];
    const float* mask   = (const float*)d_in[2];
    const float* Wa     = (const float*)d_in[3];
    const float* ba     = (const float*)d_in[4];
    const float* Wd     = (const float*)d_in[5];
    const float* bd     = (const float*)d_in[6];
    const float* Wu     = (const float*)d_in[7];
    const float* bu     = (const float*)d_in[8];
    const float* Wg     = (const float*)d_in[9];
    const float* bg     = (const float*)d_in[10];
    const float* res_w  = (const float*)d_in[11];

    float* out       = (float*)d_out;
    float* new_stack = out + (size_t)N_TOKENS * HDIM;
    float* new_mask  = new_stack + (size_t)N_TOKENS * NHEADS * SLOTS * SD;

    (void)in_sizes; (void)n_in; (void)out_size;

    k_waT<<<192, 256>>>(Wa);
    k_actions_part<<<256, 256>>>(hidden);
    k_kv<<<(N_TOKENS / 128) * NHEADS, 256>>>(hidden, Wd, bd, ba);
    k_stack_out<<<(N_TOKENS / 4) * 4, 128>>>(hidden, stack, mask, Wg, bg,
                                             Wu, bu, res_w,
                                             out, new_stack, new_mask);
}